// round 2
// baseline (speedup 1.0000x reference)
#include <cuda_runtime.h>

#define BGRAPH 64
#define HID    128
#define NCLS   10
#define MLP_BLOCKS 16   // 16 * 8 = 128 h2 columns

// Persistent scratch (allocation-free rule: __device__ globals)
// layout: [0,64)   sum_comp
//         [64,128) sum_port_col0
//         [128,192)sum_port_col1
//         [192,256)sum_net
//         [256,320)cnt_comp
//         [320,384)cnt_port
//         [384,448)cnt_net
__device__ float g_acc[7 * BGRAPH];

// ---------------------------------------------------------------------------
// K1: zero accumulators, initialize out = broadcast(bc3)
// ---------------------------------------------------------------------------
__global__ void k_init(const float* __restrict__ bc3, float* __restrict__ out) {
    int t = threadIdx.x;                 // blockDim = 512
    if (t < 7 * BGRAPH) g_acc[t] = 0.f;  // 448 < 512
    for (int i = t; i < BGRAPH * NCLS; i += blockDim.x)
        out[i] = bc3[i % NCLS];
}

// ---------------------------------------------------------------------------
// K2: fused segment-sum pooling with warp-aggregated atomics.
// Index space: [0,nc) comp | [nc,nc+np) port | [nc+np,nc+np+nn) net.
// gid arrays are sorted, so warps are gid-uniform except ~190 boundary warps.
// ---------------------------------------------------------------------------
__device__ __forceinline__ float wred(float v) {
#pragma unroll
    for (int o = 16; o; o >>= 1) v += __shfl_xor_sync(0xffffffffu, v, o);
    return v;
}

__global__ void k_pool(const float* __restrict__ hc, const float* __restrict__ hp,
                       const float* __restrict__ hn,
                       const int* __restrict__ gc, const int* __restrict__ gp,
                       const int* __restrict__ gn,
                       int nc, int np, int nn) {
    int idx = blockIdx.x * blockDim.x + threadIdx.x;
    int region = 3;           // 3 == invalid / out of range
    float v0 = 0.f, v1 = 0.f;
    int gid = -1;

    if (idx < nc) {
        region = 0;
        v0 = hc[idx];
        gid = gc[idx];
    } else if (idx < nc + np) {
        int i = idx - nc;
        region = 1;
        float2 p = reinterpret_cast<const float2*>(hp)[i];
        v0 = p.x; v1 = p.y;
        gid = gp[i];
    } else if (idx < nc + np + nn) {
        int i = idx - nc - np;
        region = 2;
        v0 = hn[i];
        gid = gn[i];
    }

    const unsigned full = 0xffffffffu;
    int r0 = __shfl_sync(full, region, 0);
    int g0 = __shfl_sync(full, gid, 0);
    bool uni = __all_sync(full, (region == r0) && (gid == g0));

    if (uni) {
        if (r0 == 3) return;                  // whole warp past the end
        float s0 = wred(v0);
        if (r0 == 1) {
            float s1 = wred(v1);
            if ((threadIdx.x & 31) == 0) {
                atomicAdd(&g_acc[64  + g0], s0);
                atomicAdd(&g_acc[128 + g0], s1);
                atomicAdd(&g_acc[320 + g0], 32.f);
            }
        } else {
            int base  = (r0 == 0) ? 0   : 192;
            int basec = (r0 == 0) ? 256 : 384;
            if ((threadIdx.x & 31) == 0) {
                atomicAdd(&g_acc[base  + g0], s0);
                atomicAdd(&g_acc[basec + g0], 32.f);
            }
        }
    } else {
        // boundary warp: per-lane atomics (rare)
        if (region == 0) {
            atomicAdd(&g_acc[gid], v0);
            atomicAdd(&g_acc[256 + gid], 1.f);
        } else if (region == 1) {
            atomicAdd(&g_acc[64  + gid], v0);
            atomicAdd(&g_acc[128 + gid], v1);
            atomicAdd(&g_acc[320 + gid], 1.f);
        } else if (region == 2) {
            atomicAdd(&g_acc[192 + gid], v0);
            atomicAdd(&g_acc[384 + gid], 1.f);
        }
    }
}

// ---------------------------------------------------------------------------
// K3: MLP. Each of MLP_BLOCKS blocks recomputes hg + full h1 (cheap), then
// computes an 8-column slice of h2 and accumulates its partial contribution
// to out (out pre-initialized to bc3 by K1).
// ---------------------------------------------------------------------------
__global__ void __launch_bounds__(512, 1)
k_mlp(const float* __restrict__ Wc1, const float* __restrict__ bc1,
      const float* __restrict__ Wc2, const float* __restrict__ bc2,
      const float* __restrict__ Wc3, float* __restrict__ out) {
    __shared__ float hg[BGRAPH][4];
    __shared__ float h1[BGRAPH][HID + 1];   // +1 pad: kills bank conflicts on h1[i][k]
    __shared__ float h2s[BGRAPH][9];        // 8 cols + pad

    int t = threadIdx.x;   // 512 threads

    if (t < BGRAPH) {
        float c0 = fmaxf(g_acc[256 + t], 1.f);
        float c1 = fmaxf(g_acc[320 + t], 1.f);
        float c2 = fmaxf(g_acc[384 + t], 1.f);
        hg[t][0] = g_acc[t]        / c0;
        hg[t][1] = g_acc[64  + t]  / c1;
        hg[t][2] = g_acc[128 + t]  / c1;
        hg[t][3] = g_acc[192 + t]  / c2;
    }
    __syncthreads();

    // ---- layer 1: h1 = relu(hg @ Wc1 + bc1), full [64,128] ----
    {
        int j  = t & (HID - 1);
        int i0 = t >> 7;                // 0..3
        float b  = bc1[j];
        float w0 = Wc1[j];
        float w1 = Wc1[HID + j];
        float w2 = Wc1[2 * HID + j];
        float w3 = Wc1[3 * HID + j];
#pragma unroll
        for (int r = 0; r < 16; r++) {
            int i = i0 * 16 + r;
            float a = b + hg[i][0] * w0 + hg[i][1] * w1 + hg[i][2] * w2 + hg[i][3] * w3;
            h1[i][j] = fmaxf(a, 0.f);
        }
    }
    __syncthreads();

    // ---- layer 2 slice: h2[:, blockIdx.x*8 + jj] ----
    {
        int i    = t >> 3;                    // 0..63
        int jj   = t & 7;                     // 0..7
        int jcol = blockIdx.x * 8 + jj;
        float acc = bc2[jcol];
#pragma unroll 8
        for (int k = 0; k < HID; k++)
            acc += h1[i][k] * Wc2[k * HID + jcol];
        h2s[i][jj] = fmaxf(acc, 0.f);
    }
    __syncthreads();

    // ---- layer 3 partial: out[i][c] += sum_{jj} h2s[i][jj] * Wc3[jcol][c] ----
    // BGRAPH*NCLS = 640 work items > 512 threads: strided loop (R1 bug fix).
    for (int tt = t; tt < BGRAPH * NCLS; tt += 512) {
        int i = tt / NCLS, c = tt % NCLS;
        float p = 0.f;
#pragma unroll
        for (int jj = 0; jj < 8; jj++)
            p += h2s[i][jj] * Wc3[(blockIdx.x * 8 + jj) * NCLS + c];
        atomicAdd(&out[i * NCLS + c], p);
    }
}

// ---------------------------------------------------------------------------
// launch
// ---------------------------------------------------------------------------
extern "C" void kernel_launch(void* const* d_in, const int* in_sizes, int n_in,
                              void* d_out, int out_size) {
    const float* h_comp = (const float*)d_in[0];
    const float* h_port = (const float*)d_in[1];
    const float* h_net  = (const float*)d_in[2];
    // d_in[3..6]: edge arrays — dead code in the reference, never read
    const int* gid_comp = (const int*)d_in[7];
    const int* gid_port = (const int*)d_in[8];
    const int* gid_net  = (const int*)d_in[9];
    // d_in[10..21]: GraphConv weights — dead code in the reference, never read
    const float* Wc1 = (const float*)d_in[22];
    const float* bc1 = (const float*)d_in[23];
    const float* Wc2 = (const float*)d_in[24];
    const float* bc2 = (const float*)d_in[25];
    const float* Wc3 = (const float*)d_in[26];
    const float* bc3 = (const float*)d_in[27];

    float* out = (float*)d_out;

    int nc = in_sizes[0];
    int np = in_sizes[1] / 2;
    int nn = in_sizes[2];
    int total = nc + np + nn;

    k_init<<<1, 512>>>(bc3, out);

    int threads = 256;
    int blocks = (total + threads - 1) / threads;
    k_pool<<<blocks, threads>>>(h_comp, h_port, h_net,
                                gid_comp, gid_port, gid_net,
                                nc, np, nn);

    k_mlp<<<MLP_BLOCKS, 512>>>(Wc1, bc1, Wc2, bc2, Wc3, out);
}